// round 1
// baseline (speedup 1.0000x reference)
#include <cuda_runtime.h>
#include <cuda_bf16.h>
#include <cstdint>

#define TOKENS  4096
#define DMODEL  512
#define VOCAB   128000
#define BM      128
#define BN      128
#define BK      64
#define NSPLITS 37
#define NTILES_N (VOCAB / BN)   /* 1000 */
#define TTILES   (TOKENS / BM)  /* 32   */

// ---------------- scratch (device globals: allocation-free rule) ----------------
__device__ __align__(16) __nv_bfloat16 g_Xb[TOKENS * DMODEL];
__device__ __align__(16) __nv_bfloat16 g_Wb[(size_t)VOCAB * DMODEL];
__device__ float g_ts[TOKENS];
__device__ float g_sum[NSPLITS * TOKENS];

// ---------------- fast exp (fma-pipe only, overlaps tensor pipe) ----------------
__device__ __forceinline__ float fast_exp(float v) {
    float t = v * 1.4426950408889634f;
    t = fminf(fmaxf(t, -126.0f), 126.0f);          // safety clamp
    float r  = t + 12582912.0f;                    // 1.5 * 2^23 round trick
    float nf = r - 12582912.0f;
    float f  = t - nf;                             // f in [-0.5, 0.5]
    int   e  = __float_as_int(r) << 23;            // n << 23 (mod 2^32, wraps correctly)
    float p  = 0.0013333558f;                      // 2^f Taylor/minimax deg-5
    p = fmaf(p, f, 0.0096181291f);
    p = fmaf(p, f, 0.0555041087f);
    p = fmaf(p, f, 0.2402265070f);
    p = fmaf(p, f, 0.6931471806f);
    p = fmaf(p, f, 1.0f);
    return p * __int_as_float(0x3f800000 + e);
}

// ---------------- conversions ----------------
__global__ void convert_x_kernel(const float* __restrict__ src) {
    int i = (blockIdx.x * blockDim.x + threadIdx.x) * 4;
    int stride = gridDim.x * blockDim.x * 4;
    for (; i < TOKENS * DMODEL; i += stride) {
        float4 v = *reinterpret_cast<const float4*>(src + i);
        __nv_bfloat162* d = reinterpret_cast<__nv_bfloat162*>(&g_Xb[i]);
        d[0] = __floats2bfloat162_rn(v.x, v.y);
        d[1] = __floats2bfloat162_rn(v.z, v.w);
    }
}

__global__ void convert_w_kernel(const float* __restrict__ src) {
    int i = (blockIdx.x * blockDim.x + threadIdx.x) * 4;
    int stride = gridDim.x * blockDim.x * 4;
    const int n = VOCAB * DMODEL;  // 65,536,000 < 2^31
    for (; i < n; i += stride) {
        float4 v = *reinterpret_cast<const float4*>(src + i);
        __nv_bfloat162* d = reinterpret_cast<__nv_bfloat162*>(&g_Wb[i]);
        d[0] = __floats2bfloat162_rn(v.x, v.y);
        d[1] = __floats2bfloat162_rn(v.z, v.w);
    }
}

// ---------------- target score (exact fp32, one warp per token) ----------------
__global__ void target_score_kernel(const float* __restrict__ x,
                                    const float* __restrict__ w,
                                    const int* __restrict__ target) {
    int t = blockIdx.x * 8 + (threadIdx.x >> 5);
    int lane = threadIdx.x & 31;
    if (t >= TOKENS) return;
    int tgt = target[t];
    const float4* xr = reinterpret_cast<const float4*>(x + (size_t)t * DMODEL);
    const float4* wr = reinterpret_cast<const float4*>(w + (size_t)tgt * DMODEL);
    float s = 0.0f;
    #pragma unroll
    for (int i = lane; i < DMODEL / 4; i += 32) {
        float4 a = xr[i]; float4 b = wr[i];
        s += a.x * b.x + a.y * b.y + a.z * b.z + a.w * b.w;
    }
    #pragma unroll
    for (int o = 16; o; o >>= 1) s += __shfl_xor_sync(0xffffffffu, s, o);
    if (lane == 0) g_ts[t] = s;
}

// ---------------- mma helpers ----------------
__device__ __forceinline__ void mma_bf16(float d[4], const uint32_t a[4],
                                         uint32_t b0, uint32_t b1) {
    asm volatile(
        "mma.sync.aligned.m16n8k16.row.col.f32.bf16.bf16.f32 "
        "{%0,%1,%2,%3},{%4,%5,%6,%7},{%8,%9},{%0,%1,%2,%3};"
        : "+f"(d[0]), "+f"(d[1]), "+f"(d[2]), "+f"(d[3])
        : "r"(a[0]), "r"(a[1]), "r"(a[2]), "r"(a[3]), "r"(b0), "r"(b1));
}

#define LDMX4(r0, r1, r2, r3, addr)                                          \
    asm volatile("ldmatrix.sync.aligned.m8n8.x4.shared.b16 {%0,%1,%2,%3},[%4];" \
                 : "=r"(r0), "=r"(r1), "=r"(r2), "=r"(r3) : "r"(addr))

// B-chunk producer: one (n-tile, k-chunk) = 128x64 bf16 via cp.async (16B ops)
__device__ __forceinline__ void issue_b(int q, int tid, int split, uint32_t Bs_u) {
    int nt = split + NSPLITS * (q >> 3);
    int kc = q & 7;
    const __nv_bfloat16* src = g_Wb + (size_t)nt * BN * DMODEL + kc * BK;
    uint32_t dst = Bs_u + (uint32_t)((q & 3) * (128 * 72 * 2));
    #pragma unroll
    for (int i = 0; i < 4; ++i) {
        int ch = tid + i * 256;          // 1024 16B chunks, 8 per row
        int row = ch >> 3, c16 = ch & 7;
        uint32_t sa = dst + (uint32_t)((row * 72 + c16 * 8) * 2);
        const void* g = (const void*)(src + (size_t)row * DMODEL + c16 * 8);
        asm volatile("cp.async.cg.shared.global [%0], [%1], 16;\n" :: "r"(sa), "l"(g));
    }
    asm volatile("cp.async.commit_group;\n" ::: "memory");
}

// ---------------- main CE partial kernel ----------------
// grid (32 token tiles, 37 vocab splits). Persistent A (128x512 bf16) in smem,
// 4-stage cp.async pipeline on B. Writes per-(split,token) sum-of-exp partials.
__global__ void __launch_bounds__(256, 1) ce_partial_kernel() {
    extern __shared__ char smem[];
    const int tid = threadIdx.x;
    const int lane = tid & 31;
    const int wid = tid >> 5;
    const int warpm = wid >> 2;   // 0..1  (64 rows each)
    const int warpn = wid & 3;    // 0..3  (32 cols each)
    const int tile_m = blockIdx.x;
    const int split  = blockIdx.y;

    __nv_bfloat16* As = reinterpret_cast<__nv_bfloat16*>(smem);                 // [128][520]
    float* red = reinterpret_cast<float*>(smem + 128 * 520 * 2 + 4 * 128 * 72 * 2);
    const uint32_t As_u = (uint32_t)__cvta_generic_to_shared(As);
    const uint32_t Bs_u = As_u + 128 * 520 * 2;

    // ---- A tile: 128x512 bf16, loaded once ----
    {
        const __nv_bfloat16* src = g_Xb + (size_t)tile_m * (BM * DMODEL);
        #pragma unroll
        for (int it = 0; it < 32; ++it) {
            int ch = tid + it * 256;      // 8192 16B chunks, 64 per row
            int row = ch >> 6, c16 = ch & 63;
            uint32_t sa = As_u + (uint32_t)((row * 520 + c16 * 8) * 2);
            const void* g = (const void*)(src + (size_t)row * DMODEL + c16 * 8);
            asm volatile("cp.async.cg.shared.global [%0], [%1], 16;\n" :: "r"(sa), "l"(g));
        }
        asm volatile("cp.async.commit_group;\n" ::: "memory");
    }

    const int ntile_cnt = (NTILES_N - 1 - split) / NSPLITS + 1;  // 27 or 28
    const int Q = ntile_cnt * 8;

    issue_b(0, tid, split, Bs_u);
    issue_b(1, tid, split, Bs_u);
    issue_b(2, tid, split, Bs_u);

    float rs[8];
    #pragma unroll
    for (int i = 0; i < 8; ++i) rs[i] = 0.0f;

    float acc[4][4][4];

    // lane-derived ldmatrix addressing
    const int a_row = warpm * 64 + ((lane >> 3) & 1) * 8 + (lane & 7);
    const int a_col = (lane >> 4) * 8;
    const int b_row = warpn * 32 + ((lane >> 4) & 1) * 8 + (lane & 7);
    const int b_col = ((lane >> 3) & 1) * 8;

    for (int q = 0; q < Q; ++q) {
        int rem = Q - 1 - q;
        if (rem >= 2)      asm volatile("cp.async.wait_group 2;\n" ::: "memory");
        else if (rem == 1) asm volatile("cp.async.wait_group 1;\n" ::: "memory");
        else               asm volatile("cp.async.wait_group 0;\n" ::: "memory");
        __syncthreads();

        int kc = q & 7;
        if (kc == 0) {
            #pragma unroll
            for (int mt = 0; mt < 4; ++mt)
                #pragma unroll
                for (int nt = 0; nt < 4; ++nt)
                    #pragma unroll
                    for (int j = 0; j < 4; ++j) acc[mt][nt][j] = 0.0f;
        }

        uint32_t bbase = Bs_u + (uint32_t)((q & 3) * (128 * 72 * 2));
        #pragma unroll
        for (int ks = 0; ks < 4; ++ks) {
            uint32_t a[4][4];
            int kA = kc * 64 + ks * 16 + a_col;
            #pragma unroll
            for (int mt = 0; mt < 4; ++mt) {
                uint32_t sa = As_u + (uint32_t)(((a_row + mt * 16) * 520 + kA) * 2);
                LDMX4(a[mt][0], a[mt][1], a[mt][2], a[mt][3], sa);
            }
            uint32_t b[2][4];
            #pragma unroll
            for (int np = 0; np < 2; ++np) {
                uint32_t sb = bbase + (uint32_t)(((b_row + np * 16) * 72 + ks * 16 + b_col) * 2);
                LDMX4(b[np][0], b[np][1], b[np][2], b[np][3], sb);
            }
            #pragma unroll
            for (int mt = 0; mt < 4; ++mt)
                #pragma unroll
                for (int np = 0; np < 2; ++np) {
                    mma_bf16(acc[mt][np * 2 + 0], a[mt], b[np][0], b[np][1]);
                    mma_bf16(acc[mt][np * 2 + 1], a[mt], b[np][2], b[np][3]);
                }
        }

        if (kc == 7) {  // tile complete: fold logits into running exp-sums
            #pragma unroll
            for (int mt = 0; mt < 4; ++mt) {
                float s0 = 0.0f, s1 = 0.0f;
                #pragma unroll
                for (int nt = 0; nt < 4; ++nt) {
                    s0 += fast_exp(acc[mt][nt][0]) + fast_exp(acc[mt][nt][1]);
                    s1 += fast_exp(acc[mt][nt][2]) + fast_exp(acc[mt][nt][3]);
                }
                rs[mt * 2 + 0] += s0;
                rs[mt * 2 + 1] += s1;
            }
        }

        if (q + 3 < Q) issue_b(q + 3, tid, split, Bs_u);
    }

    // ---- reduce: quad (n within warp) -> smem (across warpn) ----
    #pragma unroll
    for (int i = 0; i < 8; ++i) {
        rs[i] += __shfl_xor_sync(0xffffffffu, rs[i], 1);
        rs[i] += __shfl_xor_sync(0xffffffffu, rs[i], 2);
    }
    __syncthreads();
    if ((lane & 3) == 0) {
        int g = lane >> 2;
        #pragma unroll
        for (int mt = 0; mt < 4; ++mt)
            #pragma unroll
            for (int rh = 0; rh < 2; ++rh) {
                int row = warpm * 64 + mt * 16 + rh * 8 + g;
                red[row * 4 + warpn] = rs[mt * 2 + rh];
            }
    }
    __syncthreads();
    if (tid < 128) {
        float s = red[tid * 4 + 0] + red[tid * 4 + 1] + red[tid * 4 + 2] + red[tid * 4 + 3];
        g_sum[split * TOKENS + tile_m * BM + tid] = s;
    }
}

// ---------------- final loss reduce ----------------
__global__ void loss_kernel(float* __restrict__ out) {
    __shared__ float sm[256];
    float acc = 0.0f;
    for (int t = threadIdx.x; t < TOKENS; t += 256) {
        float S = 0.0f;
        #pragma unroll
        for (int s = 0; s < NSPLITS; ++s) S += g_sum[s * TOKENS + t];
        acc += logf(S) - g_ts[t];
    }
    sm[threadIdx.x] = acc;
    __syncthreads();
    #pragma unroll
    for (int o = 128; o; o >>= 1) {
        if (threadIdx.x < o) sm[threadIdx.x] += sm[threadIdx.x + o];
        __syncthreads();
    }
    if (threadIdx.x == 0) out[0] = sm[0];
}

// ---------------- launch ----------------
extern "C" void kernel_launch(void* const* d_in, const int* in_sizes, int n_in,
                              void* d_out, int out_size) {
    const float* x = (const float*)d_in[0];
    const float* w = (const float*)d_in[1];
    const int* target = (const int*)d_in[2];
    float* out = (float*)d_out;
    (void)in_sizes; (void)n_in; (void)out_size;

    const size_t SMEM = 128 * 520 * 2 + 4 * 128 * 72 * 2 + 128 * 4 * sizeof(float); // 208,896 B
    cudaFuncSetAttribute(ce_partial_kernel,
                         cudaFuncAttributeMaxDynamicSharedMemorySize, (int)SMEM);

    convert_w_kernel<<<4096, 256>>>(w);
    convert_x_kernel<<<2048, 256>>>(x);
    target_score_kernel<<<TOKENS / 8, 256>>>(x, w, target);
    ce_partial_kernel<<<dim3(TTILES, NSPLITS), 256, SMEM>>>();
    loss_kernel<<<1, 256>>>(out);
}

// round 3
// speedup vs baseline: 1.0355x; 1.0355x over previous
#include <cuda_runtime.h>
#include <cstdint>

#define TOKENS  4096
#define DMODEL  512
#define VOCAB   128000
#define BM      128
#define BN      128
#define BK      64            /* fp8 elems per k-chunk = 64 bytes */
#define NSPLITS 37
#define NTILES_N (VOCAB / BN)   /* 1000 */
#define TTILES   (TOKENS / BM)  /* 32   */

// smem strides (bytes), padded for conflict-free ldmatrix
#define ASTRIDE 528   /* 512 + 16 ; 528/16 mod 8 = 1 -> distinct granules */
#define BSTRIDE 80    /* 64 + 16  ; 80/16  mod 8 = 5 -> distinct granules */
#define BSTAGE  (128 * BSTRIDE)          /* 10240 */
#define A_BYTES (128 * ASTRIDE)          /* 67584 */
#define SMEM_TOTAL (A_BYTES + 4 * BSTAGE + 128 * 4 * 4)  /* 110592 */

// scales: x*16, W*1024 -> logits scaled 16384x ; exp(l) = 2^(l_s * log2e/16384)
#define SW_X 16.0f
#define SW_W 1024.0f
#define EPI_SCALE 8.805453862847030e-5f   /* log2(e)/16384 */

// ---------------- scratch ----------------
__device__ __align__(16) uint8_t g_X8[TOKENS * DMODEL];
__device__ __align__(16) uint8_t g_W8[(size_t)VOCAB * DMODEL];
__device__ float g_ts[TOKENS];
__device__ float g_sum[NSPLITS * TOKENS];

// ---------------- ptx helpers ----------------
__device__ __forceinline__ float ex2f(float x) {
    float r; asm("ex2.approx.f32 %0, %1;" : "=f"(r) : "f"(x)); return r;
}
__device__ __forceinline__ uint16_t cvt2_e4m3(float lo, float hi) {
    uint16_t r;
    asm("cvt.rn.satfinite.e4m3x2.f32 %0, %1, %2;" : "=h"(r) : "f"(hi), "f"(lo));
    return r;
}
__device__ __forceinline__ void mma_f8(float d[4], const uint32_t a[4],
                                       uint32_t b0, uint32_t b1) {
    asm volatile(
        "mma.sync.aligned.m16n8k32.row.col.f32.e4m3.e4m3.f32 "
        "{%0,%1,%2,%3},{%4,%5,%6,%7},{%8,%9},{%0,%1,%2,%3};"
        : "+f"(d[0]), "+f"(d[1]), "+f"(d[2]), "+f"(d[3])
        : "r"(a[0]), "r"(a[1]), "r"(a[2]), "r"(a[3]), "r"(b0), "r"(b1));
}
#define LDMX4(r0, r1, r2, r3, addr)                                          \
    asm volatile("ldmatrix.sync.aligned.m8n8.x4.shared.b16 {%0,%1,%2,%3},[%4];" \
                 : "=r"(r0), "=r"(r1), "=r"(r2), "=r"(r3) : "r"(addr))

// ---------------- fp8 conversion ----------------
__global__ void convert_w8(const float* __restrict__ src) {
    size_t i = ((size_t)blockIdx.x * blockDim.x + threadIdx.x) * 16;
    const float4* s = reinterpret_cast<const float4*>(src + i);
    float4 f0 = s[0], f1 = s[1], f2 = s[2], f3 = s[3];
    uint32_t u0 = (uint32_t)cvt2_e4m3(f0.x * SW_W, f0.y * SW_W) |
                  ((uint32_t)cvt2_e4m3(f0.z * SW_W, f0.w * SW_W) << 16);
    uint32_t u1 = (uint32_t)cvt2_e4m3(f1.x * SW_W, f1.y * SW_W) |
                  ((uint32_t)cvt2_e4m3(f1.z * SW_W, f1.w * SW_W) << 16);
    uint32_t u2 = (uint32_t)cvt2_e4m3(f2.x * SW_W, f2.y * SW_W) |
                  ((uint32_t)cvt2_e4m3(f2.z * SW_W, f2.w * SW_W) << 16);
    uint32_t u3 = (uint32_t)cvt2_e4m3(f3.x * SW_W, f3.y * SW_W) |
                  ((uint32_t)cvt2_e4m3(f3.z * SW_W, f3.w * SW_W) << 16);
    *reinterpret_cast<uint4*>(g_W8 + i) = make_uint4(u0, u1, u2, u3);
}
__global__ void convert_x8(const float* __restrict__ src) {
    size_t i = ((size_t)blockIdx.x * blockDim.x + threadIdx.x) * 16;
    const float4* s = reinterpret_cast<const float4*>(src + i);
    float4 f0 = s[0], f1 = s[1], f2 = s[2], f3 = s[3];
    uint32_t u0 = (uint32_t)cvt2_e4m3(f0.x * SW_X, f0.y * SW_X) |
                  ((uint32_t)cvt2_e4m3(f0.z * SW_X, f0.w * SW_X) << 16);
    uint32_t u1 = (uint32_t)cvt2_e4m3(f1.x * SW_X, f1.y * SW_X) |
                  ((uint32_t)cvt2_e4m3(f1.z * SW_X, f1.w * SW_X) << 16);
    uint32_t u2 = (uint32_t)cvt2_e4m3(f2.x * SW_X, f2.y * SW_X) |
                  ((uint32_t)cvt2_e4m3(f2.z * SW_X, f2.w * SW_X) << 16);
    uint32_t u3 = (uint32_t)cvt2_e4m3(f3.x * SW_X, f3.y * SW_X) |
                  ((uint32_t)cvt2_e4m3(f3.z * SW_X, f3.w * SW_X) << 16);
    *reinterpret_cast<uint4*>(g_X8 + i) = make_uint4(u0, u1, u2, u3);
}

// ---------------- target score (exact fp32) ----------------
__global__ void target_score_kernel(const float* __restrict__ x,
                                    const float* __restrict__ w,
                                    const int* __restrict__ target) {
    int t = blockIdx.x * 8 + (threadIdx.x >> 5);
    int lane = threadIdx.x & 31;
    if (t >= TOKENS) return;
    int tgt = target[t];
    const float4* xr = reinterpret_cast<const float4*>(x + (size_t)t * DMODEL);
    const float4* wr = reinterpret_cast<const float4*>(w + (size_t)tgt * DMODEL);
    float s = 0.0f;
    #pragma unroll
    for (int i = lane; i < DMODEL / 4; i += 32) {
        float4 a = xr[i]; float4 b = wr[i];
        s += a.x * b.x + a.y * b.y + a.z * b.z + a.w * b.w;
    }
    #pragma unroll
    for (int o = 16; o; o >>= 1) s += __shfl_xor_sync(0xffffffffu, s, o);
    if (lane == 0) g_ts[t] = s;
}

// B-chunk producer: one (n-tile, k-chunk) = 128 rows x 64 B via cp.async
__device__ __forceinline__ void issue_b(int q, int tid, int split, uint32_t Bs_u) {
    int nt = split + NSPLITS * (q >> 3);
    int kc = q & 7;
    const uint8_t* src = g_W8 + (size_t)nt * (BN * DMODEL) + kc * BK;
    uint32_t dst = Bs_u + (uint32_t)((q & 3) * BSTAGE);
    #pragma unroll
    for (int i = 0; i < 2; ++i) {
        int ch = tid + i * 256;          // 512 chunks of 16B, 4 per row
        int row = ch >> 2, c16 = ch & 3;
        uint32_t sa = dst + (uint32_t)(row * BSTRIDE + c16 * 16);
        const void* g = (const void*)(src + (size_t)row * DMODEL + c16 * 16);
        asm volatile("cp.async.cg.shared.global [%0], [%1], 16;\n" :: "r"(sa), "l"(g));
    }
    asm volatile("cp.async.commit_group;\n" ::: "memory");
}

// ---------------- main CE partial kernel (fp8 mma.sync) ----------------
__global__ void __launch_bounds__(256, 1) ce8_kernel() {
    extern __shared__ char smem[];
    const int tid = threadIdx.x;
    const int lane = tid & 31;
    const int wid = tid >> 5;
    const int warpm = wid >> 2;   // 0..1  (64 rows each)
    const int warpn = wid & 3;    // 0..3  (32 cols each)
    const int tile_m = blockIdx.x;
    const int split  = blockIdx.y;

    float* red = reinterpret_cast<float*>(smem + A_BYTES + 4 * BSTAGE);
    const uint32_t As_u = (uint32_t)__cvta_generic_to_shared(smem);
    const uint32_t Bs_u = As_u + A_BYTES;

    // ---- A tile: 128 x 512 fp8, loaded once ----
    {
        const uint8_t* src = g_X8 + (size_t)tile_m * (BM * DMODEL);
        #pragma unroll
        for (int it = 0; it < 16; ++it) {
            int ch = tid + it * 256;      // 4096 chunks of 16B, 32 per row
            int row = ch >> 5, c16 = ch & 31;
            uint32_t sa = As_u + (uint32_t)(row * ASTRIDE + c16 * 16);
            const void* g = (const void*)(src + (size_t)row * DMODEL + c16 * 16);
            asm volatile("cp.async.cg.shared.global [%0], [%1], 16;\n" :: "r"(sa), "l"(g));
        }
        asm volatile("cp.async.commit_group;\n" ::: "memory");
    }

    const int ntile_cnt = (NTILES_N - 1 - split) / NSPLITS + 1;  // 27 or 28
    const int Q = ntile_cnt * 8;

    issue_b(0, tid, split, Bs_u);
    issue_b(1, tid, split, Bs_u);
    issue_b(2, tid, split, Bs_u);

    float rs[8];
    #pragma unroll
    for (int i = 0; i < 8; ++i) rs[i] = 0.0f;

    float acc[4][4][4];

    // fragment addressing (byte offsets; fp8 elements are 1 byte)
    const int a_row = warpm * 64 + (lane & 15);
    const int a_csel = ((lane >> 4) & 1) * 16;
    const int b_row = warpn * 32 + ((lane >> 4) & 1) * 8 + (lane & 7);
    const int b_csel = ((lane >> 3) & 1) * 16;

    for (int q = 0; q < Q; ++q) {
        int rem = Q - 1 - q;
        if (rem >= 2)      asm volatile("cp.async.wait_group 2;\n" ::: "memory");
        else if (rem == 1) asm volatile("cp.async.wait_group 1;\n" ::: "memory");
        else               asm volatile("cp.async.wait_group 0;\n" ::: "memory");
        __syncthreads();

        int kc = q & 7;
        if (kc == 0) {
            #pragma unroll
            for (int mt = 0; mt < 4; ++mt)
                #pragma unroll
                for (int nt = 0; nt < 4; ++nt)
                    #pragma unroll
                    for (int j = 0; j < 4; ++j) acc[mt][nt][j] = 0.0f;
        }

        uint32_t bbase = Bs_u + (uint32_t)((q & 3) * BSTAGE);
        #pragma unroll
        for (int ks = 0; ks < 2; ++ks) {      // two k32 steps per 64B chunk
            int kbyte = kc * BK + ks * 32;
            uint32_t a[4][4];
            #pragma unroll
            for (int mt = 0; mt < 4; ++mt) {
                uint32_t sa = As_u + (uint32_t)((a_row + mt * 16) * ASTRIDE + kbyte + a_csel);
                LDMX4(a[mt][0], a[mt][1], a[mt][2], a[mt][3], sa);
            }
            uint32_t b[2][4];
            #pragma unroll
            for (int np = 0; np < 2; ++np) {
                uint32_t sb = bbase + (uint32_t)((b_row + np * 16) * BSTRIDE + ks * 32 + b_csel);
                LDMX4(b[np][0], b[np][1], b[np][2], b[np][3], sb);
            }
            #pragma unroll
            for (int mt = 0; mt < 4; ++mt)
                #pragma unroll
                for (int np = 0; np < 2; ++np) {
                    mma_f8(acc[mt][np * 2 + 0], a[mt], b[np][0], b[np][1]);
                    mma_f8(acc[mt][np * 2 + 1], a[mt], b[np][2], b[np][3]);
                }
        }

        if (kc == 7) {  // tile complete: fold logits into running exp-sums
            #pragma unroll
            for (int mt = 0; mt < 4; ++mt) {
                float s0 = 0.0f, s1 = 0.0f;
                #pragma unroll
                for (int nt = 0; nt < 4; ++nt) {
                    s0 += ex2f(acc[mt][nt][0] * EPI_SCALE) + ex2f(acc[mt][nt][1] * EPI_SCALE);
                    s1 += ex2f(acc[mt][nt][2] * EPI_SCALE) + ex2f(acc[mt][nt][3] * EPI_SCALE);
                }
                rs[mt * 2 + 0] += s0;
                rs[mt * 2 + 1] += s1;
            }
        }

        if (q + 3 < Q) issue_b(q + 3, tid, split, Bs_u);
    }

    // ---- reduce: quad (n within warp) -> smem (across warpn) ----
    #pragma unroll
    for (int i = 0; i < 8; ++i) {
        rs[i] += __shfl_xor_sync(0xffffffffu, rs[i], 1);
        rs[i] += __shfl_xor_sync(0xffffffffu, rs[i], 2);
    }
    __syncthreads();
    if ((lane & 3) == 0) {
        int g = lane >> 2;
        #pragma unroll
        for (int mt = 0; mt < 4; ++mt)
            #pragma unroll
            for (int rh = 0; rh < 2; ++rh) {
                int row = warpm * 64 + mt * 16 + rh * 8 + g;
                red[row * 4 + warpn] = rs[mt * 2 + rh];
            }
    }
    __syncthreads();
    if (tid < 128) {
        float s = red[tid * 4 + 0] + red[tid * 4 + 1] + red[tid * 4 + 2] + red[tid * 4 + 3];
        g_sum[split * TOKENS + tile_m * BM + tid] = s;
    }
}

// ---------------- final loss reduce ----------------
__global__ void loss_kernel(float* __restrict__ out) {
    __shared__ float sm[256];
    float acc = 0.0f;
    for (int t = threadIdx.x; t < TOKENS; t += 256) {
        float S = 0.0f;
        #pragma unroll
        for (int s = 0; s < NSPLITS; ++s) S += g_sum[s * TOKENS + t];
        acc += logf(S) - g_ts[t];
    }
    sm[threadIdx.x] = acc;
    __syncthreads();
    #pragma unroll
    for (int o = 128; o; o >>= 1) {
        if (threadIdx.x < o) sm[threadIdx.x] += sm[threadIdx.x + o];
        __syncthreads();
    }
    if (threadIdx.x == 0) out[0] = sm[0];
}

// ---------------- launch ----------------
extern "C" void kernel_launch(void* const* d_in, const int* in_sizes, int n_in,
                              void* d_out, int out_size) {
    const float* x = (const float*)d_in[0];
    const float* w = (const float*)d_in[1];
    const int* target = (const int*)d_in[2];
    float* out = (float*)d_out;
    (void)in_sizes; (void)n_in; (void)out_size;

    cudaFuncSetAttribute(ce8_kernel, cudaFuncAttributeMaxDynamicSharedMemorySize,
                         SMEM_TOTAL);

    convert_w8<<<16000, 256>>>(w);                    // 16000*256*16 = 65,536,000
    convert_x8<<<512, 256>>>(x);                      // 512*256*16  =  2,097,152
    target_score_kernel<<<TOKENS / 8, 256>>>(x, w, target);
    ce8_kernel<<<dim3(TTILES, NSPLITS), 256, SMEM_TOTAL>>>();
    loss_kernel<<<1, 256>>>(out);
}